// round 1
// baseline (speedup 1.0000x reference)
#include <cuda_runtime.h>

#define BB 16
#define CC 3
#define HH 384
#define WW 384
#define HO 382
#define WO 382

typedef unsigned long long u64;

// Packed f32x2 FMA (FFMA2) — 2x fp32 throughput on sm_103a, PTX-only.
__device__ __forceinline__ u64 ffma2(u64 a, u64 b, u64 c){
    u64 d; asm("fma.rn.f32x2 %0,%1,%2,%3;" : "=l"(d) : "l"(a), "l"(b), "l"(c)); return d;
}
__device__ __forceinline__ u64 rep2(float x){
    u64 r; asm("mov.b64 %0,{%1,%1};" : "=l"(r) : "f"(x)); return r;
}
__device__ __forceinline__ float2 unpack2(u64 v){
    float2 f; asm("mov.b64 {%0,%1},%2;" : "=f"(f.x), "=f"(f.y) : "l"(v)); return f;
}

// One thread per output pixel. Block = 32x8 tile (warp = 32 consecutive wo ->
// gather LDGs stay within ~2 cache lines). Fused: offset conv (FFMA2, channel
// pairs = (dy,dx) per tap) + bilinear deform + 3-channel einsum.
__global__ __launch_bounds__(256) void dcn_fused(
    const float* __restrict__ x,
    const float* __restrict__ conv_w,
    const float* __restrict__ conv_b,
    const float* __restrict__ dcn_w,
    const float* __restrict__ dcn_b,
    float* __restrict__ out)
{
    // Packed weights: cwp[j][o], j = c*9+ky*3+kx (27 rows, stride 20 floats =
    // 80B, 16B-aligned), so each FFMA2 reads a (w[2p],w[2p+1]) pair directly.
    __shared__ __align__(16) float cwp[27 * 20];
    __shared__ __align__(16) float cbs[20];
    __shared__ __align__(16) float dws[84];
    __shared__ __align__(16) float dbs[4];

    int tid = threadIdx.y * 32 + threadIdx.x;
    for (int idx = tid; idx < 486; idx += 256) {
        int o = idx / 27, jj = idx % 27;
        cwp[jj * 20 + o] = conv_w[idx];
    }
    if (tid < 18) cbs[tid] = conv_b[tid];
    if (tid < 81) dws[tid] = dcn_w[tid];
    if (tid < 3)  dbs[tid] = dcn_b[tid];
    __syncthreads();

    int j = blockIdx.x * 32 + threadIdx.x;
    int i = blockIdx.y * 8 + threadIdx.y;
    int b = blockIdx.z;
    if (i >= HO || j >= WO) return;

    const float* p0 = x + (size_t)b * CC * HH * WW;
    const float* p1 = p0 + HH * WW;
    const float* p2 = p1 + HH * WW;
    const float* pcs[3] = {p0, p1, p2};

    // ---- Offset conv: 9 accumulators, each f32x2 = (dy_k, dx_k) ----
    u64 off2[9];
    const u64* cb2 = (const u64*)cbs;
    #pragma unroll
    for (int p = 0; p < 9; p++) off2[p] = cb2[p];

    #pragma unroll
    for (int c = 0; c < 3; c++) {
        const float* pw = pcs[c] + i * WW + j;
        #pragma unroll
        for (int ky = 0; ky < 3; ky++) {
            #pragma unroll
            for (int kx = 0; kx < 3; kx++) {
                float xv = __ldg(pw + ky * WW + kx);
                u64 xv2 = rep2(xv);
                const u64* wrow = (const u64*)&cwp[(c * 9 + ky * 3 + kx) * 20];
                #pragma unroll
                for (int p = 0; p < 9; p++)
                    off2[p] = ffma2(xv2, wrow[p], off2[p]);
            }
        }
    }

    // ---- Deformable sampling + einsum ----
    float fi = (float)i, fj = (float)j;
    float acc0 = dbs[0], acc1 = dbs[1], acc2 = dbs[2];

    #pragma unroll
    for (int k = 0; k < 9; k++) {
        int ky = k / 3, kx = k % 3;
        float2 od = unpack2(off2[k]);           // (dy, dx)
        float py = od.x + (fi + (float)ky);
        float px = od.y + (fj + (float)kx);
        float y0f = floorf(py), x0f = floorf(px);
        float wy = py - y0f,   wx = px - x0f;
        int y0 = (int)y0f, x0 = (int)x0f;
        int y1 = y0 + 1,   x1 = x0 + 1;
        // unsigned-compare trick: one test covers <0 and >=dim
        float vy0 = ((unsigned)y0 < (unsigned)HH) ? 1.f : 0.f;
        float vy1 = ((unsigned)y1 < (unsigned)HH) ? 1.f : 0.f;
        float vx0 = ((unsigned)x0 < (unsigned)WW) ? 1.f : 0.f;
        float vx1 = ((unsigned)x1 < (unsigned)WW) ? 1.f : 0.f;
        int yc0 = min(max(y0, 0), HH - 1), yc1 = min(max(y1, 0), HH - 1);
        int xc0 = min(max(x0, 0), WW - 1), xc1 = min(max(x1, 0), WW - 1);
        int r0 = yc0 * WW, r1 = yc1 * WW;
        int i00 = r0 + xc0, i01 = r0 + xc1, i10 = r1 + xc0, i11 = r1 + xc1;
        // fold validity masks into the bilinear weights (no per-channel masking)
        float a0 = (1.f - wy) * vy0, a1 = wy * vy1;
        float b0 = (1.f - wx) * vx0, b1 = wx * vx1;
        float w00 = a0 * b0, w01 = a0 * b1, w10 = a1 * b0, w11 = a1 * b1;
        #pragma unroll
        for (int c = 0; c < 3; c++) {
            const float* pc = pcs[c];
            float g00 = __ldg(pc + i00), g01 = __ldg(pc + i01);
            float g10 = __ldg(pc + i10), g11 = __ldg(pc + i11);
            float val = fmaf(g11, w11, fmaf(g10, w10, fmaf(g01, w01, g00 * w00)));
            acc0 = fmaf(val, dws[0 * 27 + c * 9 + k], acc0);
            acc1 = fmaf(val, dws[1 * 27 + c * 9 + k], acc1);
            acc2 = fmaf(val, dws[2 * 27 + c * 9 + k], acc2);
        }
    }

    size_t ob = (size_t)b * 3 * HO * WO + (size_t)i * WO + j;
    out[ob]                        = acc0;
    out[ob + (size_t)HO * WO]      = acc1;
    out[ob + 2 * (size_t)HO * WO]  = acc2;
}

extern "C" void kernel_launch(void* const* d_in, const int* in_sizes, int n_in,
                              void* d_out, int out_size)
{
    const float* x      = (const float*)d_in[0];
    const float* conv_w = (const float*)d_in[1];
    const float* conv_b = (const float*)d_in[2];
    const float* dcn_w  = (const float*)d_in[3];
    const float* dcn_b  = (const float*)d_in[4];
    float* out = (float*)d_out;

    dim3 blk(32, 8);
    dim3 grd((WO + 31) / 32, (HO + 7) / 8, BB);
    dcn_fused<<<grd, blk>>>(x, conv_w, conv_b, dcn_w, dcn_b, out);
}